// round 10
// baseline (speedup 1.0000x reference)
#include <cuda_runtime.h>
#include <cuda_bf16.h>
#include <cstdint>

// CrossCCC via warp-level bf16 MMA (mma.sync.m16n8k16, tensor pipe).
//   j = base + 128k + m  =>  C(n) = sum_st sum_m D_st[m][m+n]
//   A[m][k] = p[base+128k+m]   (128 x 32 bf16)
//   B[u][k] = g[base+128k+u]   (384 x 32 bf16)
// Banded N: warp with m-tile m0 computes only u0 = m0 + 8t, t in [0,34)
// (the band where lag n = u-m can fall in [0,250)). Diagonal accumulation
// via smem atomicAdd into 4 tig-indexed copies (race-free by address
// analysis, 4KB total). 245 blocks, 2 CTAs/SM.

#define NL        256
#define NLAGS     250
#define KC        32                     // K per supertile
#define SUPER     (128 * KC)             // 4096
#define UW        384                    // N window
#define GWIN      (128 * (KC - 1) + UW)  // 4448
#define NTHREADS  512
#define MAXBLK    320
#define RSTRIDE   40                     // tile row stride in bf16 (20 words)

// dynamic smem layout (bytes)
#define OFF_PA    0                         // 128 x 40 bf16 = 10240
#define OFF_GB    10240                     // 384 x 40 bf16 = 30720
#define OFF_CS    (10240 + 30720)           // 4 x 256 f32   = 4096
#define SMEM_BYTES (OFF_CS + 4 * NL * 4)    // 45056

__device__ float d_Cpart[MAXBLK][NL];
__device__ float d_sums[MAXBLK][4];
__device__ unsigned int d_ticket;

__device__ __forceinline__ void mma_bf16(float& d0, float& d1, float& d2, float& d3,
                                         uint32_t a0, uint32_t a1, uint32_t a2, uint32_t a3,
                                         uint32_t b0, uint32_t b1) {
    asm volatile(
        "mma.sync.aligned.m16n8k16.row.col.f32.bf16.bf16.f32 "
        "{%0,%1,%2,%3}, {%4,%5,%6,%7}, {%8,%9}, {%0,%1,%2,%3};"
        : "+f"(d0), "+f"(d1), "+f"(d2), "+f"(d3)
        : "r"(a0), "r"(a1), "r"(a2), "r"(a3), "r"(b0), "r"(b1));
}

__global__ void __launch_bounds__(NTHREADS, 2)
ccc_mma_kernel(const float* __restrict__ p, const float* __restrict__ g,
               float* __restrict__ out, int T, int nst) {
    extern __shared__ char smem[];
    __nv_bfloat16* pa = reinterpret_cast<__nv_bfloat16*>(smem + OFF_PA);
    __nv_bfloat16* gb = reinterpret_cast<__nv_bfloat16*>(smem + OFF_GB);
    const uint32_t* pa32 = reinterpret_cast<const uint32_t*>(pa);
    const uint32_t* gb32 = reinterpret_cast<const uint32_t*>(gb);
    float* Cs = reinterpret_cast<float*>(smem + OFF_CS);   // [4][256]

    __shared__ float red[NTHREADS / 32];
    __shared__ int   s_last;

    const int tid  = threadIdx.x;
    const int wid  = tid >> 5, lane = tid & 31;
    const int gid  = lane >> 2, tig = lane & 3;
    const int m0   = (wid & 7) * 16;          // warp's m-tile
    const int half = wid >> 3;                // 0/1: first/second 17 n-tiles

    for (int i = tid; i < 4 * NL; i += NTHREADS) Cs[i] = 0.f;

    float s_p = 0.f, q_p = 0.f, s_g = 0.f, q_g = 0.f;

    for (int st = blockIdx.x; st < nst; st += gridDim.x) {
        const long long base = (long long)st * SUPER;
        const int lim = (int)min((long long)0x7FFFFFFF, (long long)T - base);
        const bool safe = (base + GWIN <= (long long)T);
        __syncthreads();   // previous tiles fully consumed

        // ---- fill pa[m][k] = p[base+128k+m], stats on p ----
#pragma unroll
        for (int it = 0; it < SUPER / NTHREADS; it++) {
            int cell = it * NTHREADS + tid;       // cell == 128k + m
            int k = cell >> 7, m = cell & 127;
            float v = 0.f;
            if (safe || cell < lim) v = p[base + cell];
            s_p += v; q_p += v * v;
            pa[m * RSTRIDE + k] = __float2bfloat16(v);
        }
        // ---- fill gb[u][k] = g[base+128k+u], stats on g (u<128 only) ----
#pragma unroll
        for (int it = 0; it < (KC * UW) / NTHREADS; it++) {
            int cell = it * NTHREADS + tid;
            int k = cell / UW, u = cell - k * UW;
            int j = (k << 7) + u;
            float v = 0.f;
            if (safe || j < lim) v = g[base + j];
            if (u < 128) { s_g += v; q_g += v * v; }
            gb[u * RSTRIDE + k] = __float2bfloat16(v);
        }
        __syncthreads();

        // ---- A fragments for both k-steps (registers) ----
        uint32_t af[2][4];
        {
            int r0 = (m0 + gid) * (RSTRIDE / 2) + tig;
            int r1 = r0 + 8 * (RSTRIDE / 2);
#pragma unroll
            for (int ks = 0; ks < 2; ks++) {
                int o = 8 * ks;
                af[ks][0] = pa32[r0 + o];
                af[ks][1] = pa32[r1 + o];
                af[ks][2] = pa32[r0 + o + 4];
                af[ks][3] = pa32[r1 + o + 4];
            }
        }

        // ---- banded mainloop: u0 = m0 + 8*(17*half + nt) ----
        float* Ct = Cs + tig * NL;
        for (int nt = 0; nt < 17; nt++) {
            const int u0 = m0 + 8 * (17 * half + nt);
            float d0 = 0.f, d1 = 0.f, d2 = 0.f, d3 = 0.f;
            const int brow = (u0 + gid) * (RSTRIDE / 2) + tig;
#pragma unroll
            for (int ks = 0; ks < 2; ks++) {
                uint32_t b0 = gb32[brow + 8 * ks];
                uint32_t b1 = gb32[brow + 8 * ks + 4];
                mma_bf16(d0, d1, d2, d3,
                         af[ks][0], af[ks][1], af[ks][2], af[ks][3], b0, b1);
            }
            // diagonal accumulate: n = u - m  (all 32 lane-addresses distinct)
            int n = u0 + 2 * tig - m0 - gid;
            if ((unsigned)n       < NLAGS) atomicAdd(Ct + n,     d0);
            if ((unsigned)(n + 1) < NLAGS) atomicAdd(Ct + n + 1, d1);
            if ((unsigned)(n - 8) < NLAGS) atomicAdd(Ct + n - 8, d2);
            if ((unsigned)(n - 7) < NLAGS) atomicAdd(Ct + n - 7, d3);
        }
    }
    __syncthreads();

    // ---- fold 4 C copies -> d_Cpart ----
    if (tid < NL)
        d_Cpart[blockIdx.x][tid] =
            (Cs[tid] + Cs[NL + tid]) + (Cs[2 * NL + tid] + Cs[3 * NL + tid]);

    // ---- block-reduce scalar sums ----
    float vals[4] = {s_p, q_p, s_g, q_g};
    for (int v = 0; v < 4; v++) {
        float x = vals[v];
#pragma unroll
        for (int off = 16; off > 0; off >>= 1)
            x += __shfl_down_sync(0xFFFFFFFFu, x, off);
        if (lane == 0) red[wid] = x;
        __syncthreads();
        if (tid == 0) {
            float s = 0.f;
            for (int w = 0; w < NTHREADS / 32; w++) s += red[w];
            d_sums[blockIdx.x][v] = s;
        }
        __syncthreads();
    }

    // ---- last-block election ----
    __threadfence();
    if (tid == 0) {
        unsigned int old = atomicAdd(&d_ticket, 1u);
        s_last = (old == gridDim.x - 1) ? 1 : 0;
    }
    __syncthreads();
    if (!s_last) return;

    // ================= finalize (last block) =================
    const int nblk = gridDim.x;
    __shared__ double sh_sums[4];
    __shared__ double prefp[NL];
    __shared__ double prefq[NL];
    __shared__ double cccsh[NL];

    double Cn = 0.0;
    if (tid < NL) {
        const int lag = tid;
        float a0 = 0.f, a1 = 0.f, a2 = 0.f, a3 = 0.f;
        int b = 0;
        for (; b + 3 < nblk; b += 4) {
            a0 += d_Cpart[b    ][lag];
            a1 += d_Cpart[b + 1][lag];
            a2 += d_Cpart[b + 2][lag];
            a3 += d_Cpart[b + 3][lag];
        }
        for (; b < nblk; b++) a0 += d_Cpart[b][lag];
        Cn = (double)((a0 + a1) + (a2 + a3));
    }

    if (tid < 128) {
        int v = tid >> 5, ln = tid & 31;
        double sv = 0.0;
        for (int b = ln; b < nblk; b += 32) sv += (double)d_sums[b][v];
#pragma unroll
        for (int off = 16; off > 0; off >>= 1)
            sv += __shfl_down_sync(0xFFFFFFFFu, sv, off);
        if (ln == 0) sh_sums[v] = sv;
    }

    if (tid < NL) {
        double w = (tid >= 1) ? (double)p[T - tid] : 0.0;
        prefp[tid] = w;
        prefq[tid] = w * w;
    }
    __syncthreads();
#pragma unroll
    for (int off = 1; off < NL; off <<= 1) {
        double a = 0.0, b = 0.0;
        if (tid < NL && tid >= off) { a = prefp[tid - off]; b = prefq[tid - off]; }
        __syncthreads();
        if (tid < NL) { prefp[tid] += a; prefq[tid] += b; }
        __syncthreads();
    }

    double ccc = 0.0;
    if (tid < NLAGS) {
        double tp = prefp[tid], tq = prefq[tid];
        const double Td  = (double)T;
        const double rT  = 1.0 / Td;
        const double rT1 = 1.0 / (Td - 1.0);
        double Sp = sh_sums[0] - tp, Qp = sh_sums[1] - tq;
        double Sg = sh_sums[2],      Qg = sh_sums[3];
        double mean_gt   = Sg * rT;
        double var_gt    = (Qg - Sg * Sg * rT) * rT1;
        double mean_pred = Sp * rT;
        double var_pred  = (Qp - Sp * Sp * rT) * rT1;
        double cov       = (Cn - mean_gt * Sp) * rT;
        double dm        = mean_gt - mean_pred;
        ccc = 2.0 * cov / (var_gt + var_pred + dm * dm);
    }
    if (tid < NL) cccsh[tid] = ccc;
    __syncthreads();
#pragma unroll
    for (int off = NL / 2; off > 0; off >>= 1) {
        if (tid < off) cccsh[tid] += cccsh[tid + off];
        __syncthreads();
    }
    if (tid == 0) {
        out[0] = (float)(1.0 - cccsh[0] / (double)NLAGS);
        d_ticket = 0;
    }
}

extern "C" void kernel_launch(void* const* d_in, const int* in_sizes, int n_in,
                              void* d_out, int out_size) {
    const float* p = (const float*)d_in[0];
    const float* g = (const float*)d_in[1];
    int T = in_sizes[0];
    int nst = (T + SUPER - 1) / SUPER;
    int grid = nst < 296 ? nst : 296;
    if (grid > MAXBLK) grid = MAXBLK;
    cudaFuncSetAttribute(ccc_mma_kernel,
                         cudaFuncAttributeMaxDynamicSharedMemorySize, SMEM_BYTES);
    ccc_mma_kernel<<<grid, NTHREADS, SMEM_BYTES>>>(p, g, (float*)d_out, T, nst);
}

// round 11
// speedup vs baseline: 1.4890x; 1.4890x over previous
#include <cuda_runtime.h>
#include <cuda_bf16.h>
#include <cstdint>

// CrossCCC via warp-level bf16 MMA; lag accumulators live in the MMA
// C-operand registers (two stride-8 sequences per thread), scattered to
// smem once at the end. Banded N (only diagonals with n in [0,250)).
//   j = base + 128k + m ; A[m][k]=p[base+128k+m] (128x32), B[u][k]=g[..+u] (384x32)

#define NL        256
#define NLAGS     250
#define KC        32
#define SUPER     (128 * KC)             // 4096
#define UW        384
#define GWIN      (128 * (KC - 1) + UW)  // 4352
#define NTHREADS  512
#define MAXBLK    256
#define W         20                     // tile row stride in 32-bit words

#define OFF_GB    10240                  // pa: 128*40 bf16 = 10240 B
#define TILE_BYTES (OFF_GB + 384 * W * 4)   // 40960
#define SMEM_BYTES 65536                 // Cs [64][256] f32 aliases tiles

__device__ float d_Cpart[MAXBLK][NL];
__device__ float d_sums[MAXBLK][4];
__device__ unsigned int d_ticket;

__device__ __forceinline__ uint32_t pack_bf16x2(float lo, float hi) {
    uint32_t r;
    asm("cvt.rn.bf16x2.f32 %0, %1, %2;" : "=r"(r) : "f"(hi), "f"(lo));
    return r;
}
__device__ __forceinline__ void mma_bf16(float& d0, float& d1, float& d2, float& d3,
                                         uint32_t a0, uint32_t a1, uint32_t a2, uint32_t a3,
                                         uint32_t b0, uint32_t b1) {
    asm volatile(
        "mma.sync.aligned.m16n8k16.row.col.f32.bf16.bf16.f32 "
        "{%0,%1,%2,%3}, {%4,%5,%6,%7}, {%8,%9}, {%0,%1,%2,%3};"
        : "+f"(d0), "+f"(d1), "+f"(d2), "+f"(d3)
        : "r"(a0), "r"(a1), "r"(a2), "r"(a3), "r"(b0), "r"(b1));
}

__global__ void __launch_bounds__(NTHREADS, 2)
ccc_mma_kernel(const float* __restrict__ p, const float* __restrict__ g,
               float* __restrict__ out, int T, int nst) {
    extern __shared__ char smem[];
    uint32_t* pa32 = reinterpret_cast<uint32_t*>(smem);
    uint32_t* gb32 = reinterpret_cast<uint32_t*>(smem + OFF_GB);
    float*    Cs   = reinterpret_cast<float*>(smem);   // aliases tiles (used after sync)

    __shared__ float Cfold[2][NL];
    __shared__ float red[NTHREADS / 32];
    __shared__ int   s_last;

    const int tid  = threadIdx.x;
    const int wid  = tid >> 5, lane = tid & 31;
    const int gid  = lane >> 2, tig = lane & 3;
    const int m0   = (wid & 7) * 16;
    const int half = wid >> 3;

    float acc0[18], acc1[18];
#pragma unroll
    for (int s = 0; s < 18; s++) { acc0[s] = 0.f; acc1[s] = 0.f; }
    float s_p = 0.f, q_p = 0.f, s_g = 0.f, q_g = 0.f;

    for (int st = blockIdx.x; st < nst; st += gridDim.x) {
        const long long base = (long long)st * SUPER;
        const int lim = (int)min((long long)0x7FFFFFFF, (long long)T - base);
        const bool safe = (base + GWIN <= (long long)T);
        __syncthreads();

        // ---- pa fill: word cells (m, k2); lane pattern: 8 m x 4 k2 ----
#pragma unroll
        for (int it = 0; it < 4; it++) {
            int c = it * NTHREADS + tid;
            int m = (c >> 2) & 127;
            int k2 = (c & 3) | (it << 2);
            int j0 = 256 * k2 + m;
            float v0, v1;
            if (safe) { v0 = p[base + j0]; v1 = p[base + j0 + 128]; }
            else {
                v0 = (j0       < lim) ? p[base + j0]       : 0.f;
                v1 = (j0 + 128 < lim) ? p[base + j0 + 128] : 0.f;
            }
            s_p += v0 + v1; q_p += v0 * v0 + v1 * v1;
            pa32[m * W + k2] = pack_bf16x2(v0, v1);
        }
        // ---- gb fill: word cells (u, k2) ----
#pragma unroll
        for (int it = 0; it < 12; it++) {
            const int chunk = it % 3, k2hi = it / 3;
            int c = it * NTHREADS + tid;
            int u = chunk * 128 + ((c >> 2) & 127);
            int k2 = (c & 3) | (k2hi << 2);
            int j0 = 256 * k2 + u;
            float v0, v1;
            if (safe) { v0 = g[base + j0]; v1 = g[base + j0 + 128]; }
            else {
                v0 = (j0       < lim) ? g[base + j0]       : 0.f;
                v1 = (j0 + 128 < lim) ? g[base + j0 + 128] : 0.f;
            }
            if (chunk == 0) { s_g += v0 + v1; q_g += v0 * v0 + v1 * v1; }
            gb32[u * W + k2] = pack_bf16x2(v0, v1);
        }
        __syncthreads();

        // ---- A fragments (both k-steps) ----
        uint32_t af[2][4];
        {
            int r0 = (m0 + gid) * W + tig;
#pragma unroll
            for (int ks = 0; ks < 2; ks++) {
                int o = 8 * ks;
                af[ks][0] = pa32[r0 + o];
                af[ks][1] = pa32[r0 + 8 * W + o];
                af[ks][2] = pa32[r0 + o + 4];
                af[ks][3] = pa32[r0 + 8 * W + o + 4];
            }
        }

        // ---- banded mainloop: accumulators ARE the MMA C registers ----
#pragma unroll
        for (int t = 0; t < 17; t++) {
            const int u0 = m0 + 8 * (17 * half + t);
            const int brow = (u0 + gid) * W + tig;
#pragma unroll
            for (int ks = 0; ks < 2; ks++) {
                uint32_t b0 = gb32[brow + 8 * ks];
                uint32_t b1 = gb32[brow + 8 * ks + 4];
                mma_bf16(acc0[t + 1], acc1[t + 1], acc0[t], acc1[t],
                         af[ks][0], af[ks][1], af[ks][2], af[ks][3], b0, b1);
            }
        }
    }
    __syncthreads();   // tiles dead; Cs may now alias them

    // ---- zero Cs, then scatter accumulators once ----
    for (int i = tid; i < 64 * NL; i += NTHREADS) Cs[i] = 0.f;
    __syncthreads();
    {
        float* Crow = Cs + (wid * 4 + tig) * NL;
        const int bn = 136 * half + 2 * tig - gid;
#pragma unroll
        for (int s = 0; s < 18; s++) {
            int n = bn + 8 * s - 8;
            if ((unsigned)n < NLAGS) Crow[n] += acc0[s];
        }
        __syncwarp();
#pragma unroll
        for (int s = 0; s < 18; s++) {
            int n = bn + 8 * s - 7;
            if ((unsigned)n < NLAGS) Crow[n] += acc1[s];
        }
    }
    __syncthreads();

    // ---- fold 64 rows -> d_Cpart ----
    {
        int n = tid & 255, grp = tid >> 8;
        float v = 0.f;
        for (int a = grp * 32; a < grp * 32 + 32; a++) v += Cs[a * NL + n];
        Cfold[grp][n] = v;
    }
    __syncthreads();
    if (tid < NL) d_Cpart[blockIdx.x][tid] = Cfold[0][tid] + Cfold[1][tid];

    // ---- block-reduce scalar sums ----
    float vals[4] = {s_p, q_p, s_g, q_g};
    for (int v = 0; v < 4; v++) {
        float x = vals[v];
#pragma unroll
        for (int off = 16; off > 0; off >>= 1)
            x += __shfl_down_sync(0xFFFFFFFFu, x, off);
        if (lane == 0) red[wid] = x;
        __syncthreads();
        if (tid == 0) {
            float s = 0.f;
            for (int w = 0; w < NTHREADS / 32; w++) s += red[w];
            d_sums[blockIdx.x][v] = s;
        }
        __syncthreads();
    }

    // ---- last-block election ----
    __threadfence();
    if (tid == 0) {
        unsigned int old = atomicAdd(&d_ticket, 1u);
        s_last = (old == gridDim.x - 1) ? 1 : 0;
    }
    __syncthreads();
    if (!s_last) return;

    // ================= finalize (last block) =================
    const int nblk = gridDim.x;
    __shared__ double sh_sums[4];
    __shared__ double prefp[NL];
    __shared__ double prefq[NL];
    __shared__ double cccsh[NL];

    double Cn = 0.0;
    if (tid < NL) {
        const int lag = tid;
        float a0 = 0.f, a1 = 0.f, a2 = 0.f, a3 = 0.f;
        int b = 0;
        for (; b + 3 < nblk; b += 4) {
            a0 += d_Cpart[b    ][lag];
            a1 += d_Cpart[b + 1][lag];
            a2 += d_Cpart[b + 2][lag];
            a3 += d_Cpart[b + 3][lag];
        }
        for (; b < nblk; b++) a0 += d_Cpart[b][lag];
        Cn = (double)((a0 + a1) + (a2 + a3));
    }

    if (tid < 128) {
        int v = tid >> 5, ln = tid & 31;
        double sv = 0.0;
        for (int b = ln; b < nblk; b += 32) sv += (double)d_sums[b][v];
#pragma unroll
        for (int off = 16; off > 0; off >>= 1)
            sv += __shfl_down_sync(0xFFFFFFFFu, sv, off);
        if (ln == 0) sh_sums[v] = sv;
    }

    if (tid < NL) {
        double w = (tid >= 1) ? (double)p[T - tid] : 0.0;
        prefp[tid] = w;
        prefq[tid] = w * w;
    }
    __syncthreads();
#pragma unroll
    for (int off = 1; off < NL; off <<= 1) {
        double a = 0.0, b = 0.0;
        if (tid < NL && tid >= off) { a = prefp[tid - off]; b = prefq[tid - off]; }
        __syncthreads();
        if (tid < NL) { prefp[tid] += a; prefq[tid] += b; }
        __syncthreads();
    }

    double ccc = 0.0;
    if (tid < NLAGS) {
        double tp = prefp[tid], tq = prefq[tid];
        const double Td  = (double)T;
        const double rT  = 1.0 / Td;
        const double rT1 = 1.0 / (Td - 1.0);
        double Sp = sh_sums[0] - tp, Qp = sh_sums[1] - tq;
        double Sg = sh_sums[2],      Qg = sh_sums[3];
        double mean_gt   = Sg * rT;
        double var_gt    = (Qg - Sg * Sg * rT) * rT1;
        double mean_pred = Sp * rT;
        double var_pred  = (Qp - Sp * Sp * rT) * rT1;
        double cov       = (Cn - mean_gt * Sp) * rT;
        double dm        = mean_gt - mean_pred;
        ccc = 2.0 * cov / (var_gt + var_pred + dm * dm);
    }
    if (tid < NL) cccsh[tid] = ccc;
    __syncthreads();
#pragma unroll
    for (int off = NL / 2; off > 0; off >>= 1) {
        if (tid < off) cccsh[tid] += cccsh[tid + off];
        __syncthreads();
    }
    if (tid == 0) {
        out[0] = (float)(1.0 - cccsh[0] / (double)NLAGS);
        d_ticket = 0;
    }
}

extern "C" void kernel_launch(void* const* d_in, const int* in_sizes, int n_in,
                              void* d_out, int out_size) {
    const float* p = (const float*)d_in[0];
    const float* g = (const float*)d_in[1];
    int T = in_sizes[0];
    int nst = (T + SUPER - 1) / SUPER;
    int grid = nst < MAXBLK ? nst : MAXBLK;
    cudaFuncSetAttribute(ccc_mma_kernel,
                         cudaFuncAttributeMaxDynamicSharedMemorySize, SMEM_BYTES);
    ccc_mma_kernel<<<grid, NTHREADS, SMEM_BYTES>>>(p, g, (float*)d_out, T, nst);
}

// round 12
// speedup vs baseline: 1.6117x; 1.0824x over previous
#include <cuda_runtime.h>
#include <cuda_bf16.h>
#include <cstdint>

// CrossCCC via warp-level bf16 MMA. Per-tile independent accumulators
// (17-way MMA ILP), folded into per-thread lag registers with FADDs,
// scattered to smem once at the end. Banded N (only n in [0,250)).
//   j = base + 128k + m ; A[m][k]=p[base+128k+m] (128x32), B[u][k]=g[..+u] (384x32)

#define NL        256
#define NLAGS     250
#define KC        32
#define SUPER     (128 * KC)             // 4096
#define UW        384
#define GWIN      (128 * (KC - 1) + UW)  // 4448
#define NTHREADS  512
#define MAXBLK    256
#define W         20                     // tile row stride in 32-bit words

#define OFF_GB    10240                  // pa: 128*40 bf16 = 10240 B
#define SMEM_BYTES 65536                 // Cs [64][256] f32 aliases tiles

__device__ float d_Cpart[MAXBLK][NL];
__device__ float d_sums[MAXBLK][4];
__device__ unsigned int d_ticket;

__device__ __forceinline__ uint32_t pack_bf16x2(float lo, float hi) {
    uint32_t r;
    asm("cvt.rn.bf16x2.f32 %0, %1, %2;" : "=r"(r) : "f"(hi), "f"(lo));
    return r;
}
__device__ __forceinline__ void mma_bf16(float& d0, float& d1, float& d2, float& d3,
                                         uint32_t a0, uint32_t a1, uint32_t a2, uint32_t a3,
                                         uint32_t b0, uint32_t b1) {
    asm volatile(
        "mma.sync.aligned.m16n8k16.row.col.f32.bf16.bf16.f32 "
        "{%0,%1,%2,%3}, {%4,%5,%6,%7}, {%8,%9}, {%0,%1,%2,%3};"
        : "+f"(d0), "+f"(d1), "+f"(d2), "+f"(d3)
        : "r"(a0), "r"(a1), "r"(a2), "r"(a3), "r"(b0), "r"(b1));
}

__global__ void __launch_bounds__(NTHREADS, 2)
ccc_mma_kernel(const float* __restrict__ p, const float* __restrict__ g,
               float* __restrict__ out, int T, int nst) {
    extern __shared__ char smem[];
    uint32_t* pa32 = reinterpret_cast<uint32_t*>(smem);
    uint32_t* gb32 = reinterpret_cast<uint32_t*>(smem + OFF_GB);
    float*    Cs   = reinterpret_cast<float*>(smem);   // aliases tiles (post-sync)

    __shared__ float Cfold[2][NL];
    __shared__ float red[NTHREADS / 32];
    __shared__ int   s_last;

    const int tid  = threadIdx.x;
    const int wid  = tid >> 5, lane = tid & 31;
    const int gid  = lane >> 2, tig = lane & 3;
    const int m0   = (wid & 7) * 16;
    const int half = wid >> 3;

    float acc0[18], acc1[18];
#pragma unroll
    for (int s = 0; s < 18; s++) { acc0[s] = 0.f; acc1[s] = 0.f; }
    float s_p = 0.f, q_p = 0.f, s_g = 0.f, q_g = 0.f;

    for (int st = blockIdx.x; st < nst; st += gridDim.x) {
        const long long base = (long long)st * SUPER;
        const int lim = (int)min((long long)0x7FFFFFFF, (long long)T - base);
        const bool safe = (base + GWIN <= (long long)T);
        __syncthreads();

        // ---- pa fill: word cells (m, k2); lane pattern: 8 m x 4 k2 ----
#pragma unroll
        for (int it = 0; it < 4; it++) {
            int c = it * NTHREADS + tid;
            int m = (c >> 2) & 127;
            int k2 = (c & 3) | (it << 2);
            int j0 = 256 * k2 + m;
            float v0, v1;
            if (safe) { v0 = p[base + j0]; v1 = p[base + j0 + 128]; }
            else {
                v0 = (j0       < lim) ? p[base + j0]       : 0.f;
                v1 = (j0 + 128 < lim) ? p[base + j0 + 128] : 0.f;
            }
            s_p += v0 + v1; q_p += v0 * v0 + v1 * v1;
            pa32[m * W + k2] = pack_bf16x2(v0, v1);
        }
        // ---- gb fill: word cells (u, k2) ----
#pragma unroll
        for (int it = 0; it < 12; it++) {
            const int chunk = it % 3, k2hi = it / 3;
            int c = it * NTHREADS + tid;
            int u = chunk * 128 + ((c >> 2) & 127);
            int k2 = (c & 3) | (k2hi << 2);
            int j0 = 256 * k2 + u;
            float v0, v1;
            if (safe) { v0 = g[base + j0]; v1 = g[base + j0 + 128]; }
            else {
                v0 = (j0       < lim) ? g[base + j0]       : 0.f;
                v1 = (j0 + 128 < lim) ? g[base + j0 + 128] : 0.f;
            }
            if (chunk == 0) { s_g += v0 + v1; q_g += v0 * v0 + v1 * v1; }
            gb32[u * W + k2] = pack_bf16x2(v0, v1);
        }
        __syncthreads();

        // ---- A fragments (both k-steps) ----
        uint32_t af[2][4];
        {
            int r0 = (m0 + gid) * W + tig;
#pragma unroll
            for (int ks = 0; ks < 2; ks++) {
                int o = 8 * ks;
                af[ks][0] = pa32[r0 + o];
                af[ks][1] = pa32[r0 + 8 * W + o];
                af[ks][2] = pa32[r0 + o + 4];
                af[ks][3] = pa32[r0 + 8 * W + o + 4];
            }
        }

        // ---- banded mainloop: independent per-tile accumulators ----
#pragma unroll
        for (int t = 0; t < 17; t++) {
            const int u0 = m0 + 8 * (17 * half + t);
            const int brow = (u0 + gid) * W + tig;
            float d0 = 0.f, d1 = 0.f, d2 = 0.f, d3 = 0.f;
#pragma unroll
            for (int ks = 0; ks < 2; ks++) {
                uint32_t b0 = gb32[brow + 8 * ks];
                uint32_t b1 = gb32[brow + 8 * ks + 4];
                mma_bf16(d0, d1, d2, d3,
                         af[ks][0], af[ks][1], af[ks][2], af[ks][3], b0, b1);
            }
            acc0[t + 1] += d0;
            acc1[t + 1] += d1;
            acc0[t]     += d2;
            acc1[t]     += d3;
        }
    }
    __syncthreads();   // tiles dead; Cs may now alias them

    // ---- zero Cs, then scatter accumulators once ----
    for (int i = tid; i < 64 * NL; i += NTHREADS) Cs[i] = 0.f;
    __syncthreads();
    {
        float* Crow = Cs + (wid * 4 + tig) * NL;
        const int bn = 136 * half + 2 * tig - gid;
#pragma unroll
        for (int s = 0; s < 18; s++) {
            int n = bn + 8 * s - 8;
            if ((unsigned)n < NLAGS) Crow[n] += acc0[s];
        }
        __syncwarp();
#pragma unroll
        for (int s = 0; s < 18; s++) {
            int n = bn + 8 * s - 7;
            if ((unsigned)n < NLAGS) Crow[n] += acc1[s];
        }
    }
    __syncthreads();

    // ---- fold 64 rows -> d_Cpart ----
    {
        int n = tid & 255, grp = tid >> 8;
        float v = 0.f;
        for (int a = grp * 32; a < grp * 32 + 32; a++) v += Cs[a * NL + n];
        Cfold[grp][n] = v;
    }
    __syncthreads();
    if (tid < NL) d_Cpart[blockIdx.x][tid] = Cfold[0][tid] + Cfold[1][tid];

    // ---- block-reduce scalar sums ----
    float vals[4] = {s_p, q_p, s_g, q_g};
    for (int v = 0; v < 4; v++) {
        float x = vals[v];
#pragma unroll
        for (int off = 16; off > 0; off >>= 1)
            x += __shfl_down_sync(0xFFFFFFFFu, x, off);
        if (lane == 0) red[wid] = x;
        __syncthreads();
        if (tid == 0) {
            float s = 0.f;
            for (int w = 0; w < NTHREADS / 32; w++) s += red[w];
            d_sums[blockIdx.x][v] = s;
        }
        __syncthreads();
    }

    // ---- last-block election ----
    __threadfence();
    if (tid == 0) {
        unsigned int old = atomicAdd(&d_ticket, 1u);
        s_last = (old == gridDim.x - 1) ? 1 : 0;
    }
    __syncthreads();
    if (!s_last) return;

    // ================= finalize (last block) =================
    const int nblk = gridDim.x;
    __shared__ double sh_sums[4];
    __shared__ double prefp[NL];
    __shared__ double prefq[NL];
    __shared__ double cccsh[NL];

    double Cn = 0.0;
    if (tid < NL) {
        const int lag = tid;
        float a0 = 0.f, a1 = 0.f, a2 = 0.f, a3 = 0.f;
        int b = 0;
        for (; b + 3 < nblk; b += 4) {
            a0 += d_Cpart[b    ][lag];
            a1 += d_Cpart[b + 1][lag];
            a2 += d_Cpart[b + 2][lag];
            a3 += d_Cpart[b + 3][lag];
        }
        for (; b < nblk; b++) a0 += d_Cpart[b][lag];
        Cn = (double)((a0 + a1) + (a2 + a3));
    }

    if (tid < 128) {
        int v = tid >> 5, ln = tid & 31;
        double sv = 0.0;
        for (int b = ln; b < nblk; b += 32) sv += (double)d_sums[b][v];
#pragma unroll
        for (int off = 16; off > 0; off >>= 1)
            sv += __shfl_down_sync(0xFFFFFFFFu, sv, off);
        if (ln == 0) sh_sums[v] = sv;
    }

    if (tid < NL) {
        double w = (tid >= 1) ? (double)p[T - tid] : 0.0;
        prefp[tid] = w;
        prefq[tid] = w * w;
    }
    __syncthreads();
#pragma unroll
    for (int off = 1; off < NL; off <<= 1) {
        double a = 0.0, b = 0.0;
        if (tid < NL && tid >= off) { a = prefp[tid - off]; b = prefq[tid - off]; }
        __syncthreads();
        if (tid < NL) { prefp[tid] += a; prefq[tid] += b; }
        __syncthreads();
    }

    double ccc = 0.0;
    if (tid < NLAGS) {
        double tp = prefp[tid], tq = prefq[tid];
        const double Td  = (double)T;
        const double rT  = 1.0 / Td;
        const double rT1 = 1.0 / (Td - 1.0);
        double Sp = sh_sums[0] - tp, Qp = sh_sums[1] - tq;
        double Sg = sh_sums[2],      Qg = sh_sums[3];
        double mean_gt   = Sg * rT;
        double var_gt    = (Qg - Sg * Sg * rT) * rT1;
        double mean_pred = Sp * rT;
        double var_pred  = (Qp - Sp * Sp * rT) * rT1;
        double cov       = (Cn - mean_gt * Sp) * rT;
        double dm        = mean_gt - mean_pred;
        ccc = 2.0 * cov / (var_gt + var_pred + dm * dm);
    }
    if (tid < NL) cccsh[tid] = ccc;
    __syncthreads();
#pragma unroll
    for (int off = NL / 2; off > 0; off >>= 1) {
        if (tid < off) cccsh[tid] += cccsh[tid + off];
        __syncthreads();
    }
    if (tid == 0) {
        out[0] = (float)(1.0 - cccsh[0] / (double)NLAGS);
        d_ticket = 0;
    }
}

extern "C" void kernel_launch(void* const* d_in, const int* in_sizes, int n_in,
                              void* d_out, int out_size) {
    const float* p = (const float*)d_in[0];
    const float* g = (const float*)d_in[1];
    int T = in_sizes[0];
    int nst = (T + SUPER - 1) / SUPER;
    int grid = nst < MAXBLK ? nst : MAXBLK;
    cudaFuncSetAttribute(ccc_mma_kernel,
                         cudaFuncAttributeMaxDynamicSharedMemorySize, SMEM_BYTES);
    ccc_mma_kernel<<<grid, NTHREADS, SMEM_BYTES>>>(p, g, (float*)d_out, T, nst);
}